// round 3
// baseline (speedup 1.0000x reference)
#include <cuda_runtime.h>
#include <cuda_fp16.h>
#include <cstdint>

// ---------------------------------------------------------------------------
// out[m, c] = sum_f sin(2*pi*f*t[m])*As[c,f] + cos(2*pi*f*t[m])*Ac[c,f]
// GEMM: M = 262144, N = 256, K = 256 (K = [sin | cos] frequency halves).
// Baseline-PTX tensor path: mma.sync.m16n8k16.f32.f16.f16.f32 + ldmatrix
// (tcgen05 is rejected: harness compiles for target sm_103, not sm_103a).
// Persistent CTAs (1/SM): W kept fp16 in SMEM; X tile recomputed per 64 rows.
// ---------------------------------------------------------------------------

#define NT        256
#define MT        64
// SMEM layout (bytes):
//   W: 256 rows(c) x 256 k fp16, 512 B/row, XOR-swizzled  -> 131072
//   X:  64 rows(m) x 256 k fp16, 512 B/row, XOR-swizzled  ->  32768
//   F: 128 floats (freqs)                                 ->    512
#define SW_OFF    0
#define SX_OFF    131072
#define SF_OFF    163840
#define SMEM_TOTAL 164352

static __device__ __forceinline__ uint32_t smem_u32(const void* p) {
    uint32_t a;
    asm("{ .reg .u64 t; cvta.to.shared.u64 t, %1; cvt.u32.u64 %0, t; }"
        : "=r"(a) : "l"(p));
    return a;
}

// byte offset of element (row, k) in a 512 B/row fp16 tile with 16B-chunk
// XOR swizzle: chunk' = chunk ^ (row & 7). Conflict-free for ldmatrix.
static __device__ __forceinline__ uint32_t swz(uint32_t row, uint32_t chunk) {
    return row * 512u + ((chunk ^ (row & 7u)) << 4);
}

#define LDSM_X4(r, addr) \
    asm volatile("ldmatrix.sync.aligned.m8n8.x4.shared.b16 {%0,%1,%2,%3}, [%4];" \
        : "=r"((r)[0]), "=r"((r)[1]), "=r"((r)[2]), "=r"((r)[3]) : "r"(addr))

#define MMA_16816(d, a, b0, b1) \
    asm volatile("mma.sync.aligned.m16n8k16.row.col.f32.f16.f16.f32 " \
        "{%0,%1,%2,%3}, {%4,%5,%6,%7}, {%8,%9}, {%0,%1,%2,%3};" \
        : "+f"((d)[0]), "+f"((d)[1]), "+f"((d)[2]), "+f"((d)[3]) \
        : "r"((a)[0]), "r"((a)[1]), "r"((a)[2]), "r"((a)[3]), \
          "r"(b0), "r"(b1))

__global__ void __launch_bounds__(NT, 1)
fourier_mma_kernel(const float* __restrict__ t,
                   const float* __restrict__ freqs,
                   const float* __restrict__ As,
                   const float* __restrict__ Ac,
                   float* __restrict__ out,
                   int rows)
{
    extern __shared__ char smem[];
    char* sW = smem + SW_OFF;
    char* sX = smem + SX_OFF;
    float* sF = (float*)(smem + SF_OFF);
    const uint32_t uW = smem_u32(sW);
    const uint32_t uX = smem_u32(sX);

    const int tid  = threadIdx.x;
    const int lane = tid & 31;
    const int wid  = tid >> 5;

    // ---- one-time: freqs + W fp32->fp16 into swizzled SMEM ----------------
    if (tid < 128) sF[tid] = freqs[tid];
    for (int i = tid; i < 256 * 64; i += NT) {      // 64 float4-chunks per row
        const int n  = i >> 6;
        const int j4 = i & 63;                      // k0 = 4*j4
        const int k0 = j4 << 2;
        const float* src = (k0 < 128) ? (As + n * 128 + k0)
                                      : (Ac + n * 128 + (k0 - 128));
        const float4 w = *reinterpret_cast<const float4*>(src);
        __half2 h0 = __floats2half2_rn(w.x, w.y);
        __half2 h1 = __floats2half2_rn(w.z, w.w);
        // chunk = k0/8 = j4>>1 ; 8B offset inside chunk = (j4&1)*8
        uint32_t byte = swz((uint32_t)n, (uint32_t)(j4 >> 1)) + ((uint32_t)(j4 & 1) << 3);
        uint2 v;
        v.x = *reinterpret_cast<uint32_t*>(&h0);
        v.y = *reinterpret_cast<uint32_t*>(&h1);
        *reinterpret_cast<uint2*>(sW + byte) = v;
    }
    __syncthreads();

    // ---- per-thread constants ---------------------------------------------
    const int xrow = tid >> 2;                 // X-fill: 4 threads per row
    const int f0   = (tid & 3) << 5;           // each covers 32 freqs

    const int wm = wid >> 2;                   // warp grid: 2 (M) x 4 (N)
    const int wn = wid & 3;
    const int gid = lane >> 2, tig = lane & 3;

    const int aRow0 = wm * 32 + (lane & 15);   // ldmatrix A lane row
    const int aHi   = lane >> 4;               // k-half select
    const int bRowOff = (lane & 7) + ((lane >> 4) << 3);  // B: two n-tiles
    const int bHi     = (lane >> 3) & 1;

    const int numTiles = rows / MT;

    for (int tile = blockIdx.x; tile < numTiles; tile += gridDim.x) {
        const int m0 = tile * MT;
        const float tv = t[m0 + xrow];

        // ---- fill X tile: k<128 -> sin, k>=128 -> cos ---------------------
        #pragma unroll
        for (int j = 0; j < 8; j++) {
            const int f = f0 + j * 4;
            const float4 fr = *reinterpret_cast<const float4*>(sF + f);
            float s0, c0, s1, c1, s2, c2, s3, c3;
            float h, r, th;
            h = tv * fr.x; r = (h + 12582912.0f) - 12582912.0f;
            th = (h - r) * 6.283185307179586f; __sincosf(th, &s0, &c0);
            h = tv * fr.y; r = (h + 12582912.0f) - 12582912.0f;
            th = (h - r) * 6.283185307179586f; __sincosf(th, &s1, &c1);
            h = tv * fr.z; r = (h + 12582912.0f) - 12582912.0f;
            th = (h - r) * 6.283185307179586f; __sincosf(th, &s2, &c2);
            h = tv * fr.w; r = (h + 12582912.0f) - 12582912.0f;
            th = (h - r) * 6.283185307179586f; __sincosf(th, &s3, &c3);

            __half2 hs0 = __floats2half2_rn(s0, s1), hs1 = __floats2half2_rn(s2, s3);
            __half2 hc0 = __floats2half2_rn(c0, c1), hc1 = __floats2half2_rn(c2, c3);

            const uint32_t off = ((uint32_t)(j & 1)) << 3;  // 8B within chunk
            const uint32_t ch  = (uint32_t)(f >> 3);
            const uint32_t byteS = swz((uint32_t)xrow, ch) + off;
            const uint32_t byteC = swz((uint32_t)xrow, ch + 16u) + off;
            uint2 vs, vc;
            vs.x = *reinterpret_cast<uint32_t*>(&hs0);
            vs.y = *reinterpret_cast<uint32_t*>(&hs1);
            vc.x = *reinterpret_cast<uint32_t*>(&hc0);
            vc.y = *reinterpret_cast<uint32_t*>(&hc1);
            *reinterpret_cast<uint2*>(sX + byteS) = vs;
            *reinterpret_cast<uint2*>(sX + byteC) = vc;
        }
        __syncthreads();

        // ---- MMA: warp tile 32(M) x 64(N), K = 256 ------------------------
        float acc[2][8][4];
        #pragma unroll
        for (int mi = 0; mi < 2; mi++)
            #pragma unroll
            for (int ni = 0; ni < 8; ni++)
                #pragma unroll
                for (int q = 0; q < 4; q++) acc[mi][ni][q] = 0.0f;

        #pragma unroll
        for (int ks = 0; ks < 16; ks++) {
            uint32_t a[2][4];
            #pragma unroll
            for (int mi = 0; mi < 2; mi++) {
                const uint32_t row = (uint32_t)(aRow0 + mi * 16);
                const uint32_t addr = uX + swz(row, (uint32_t)(ks * 2 + aHi));
                LDSM_X4(a[mi], addr);
            }
            uint32_t b[4][4];
            #pragma unroll
            for (int nt = 0; nt < 4; nt++) {
                const uint32_t n = (uint32_t)(wn * 64 + nt * 16 + bRowOff);
                const uint32_t addr = uW + swz(n, (uint32_t)(ks * 2 + bHi));
                LDSM_X4(b[nt], addr);
            }
            #pragma unroll
            for (int mi = 0; mi < 2; mi++)
                #pragma unroll
                for (int ni = 0; ni < 8; ni++) {
                    const uint32_t* bb = &b[ni >> 1][(ni & 1) * 2];
                    MMA_16816(acc[mi][ni], a[mi], bb[0], bb[1]);
                }
        }
        __syncthreads();   // all warps done reading sX before next fill

        // ---- epilogue: regs -> gmem (STG.64) ------------------------------
        #pragma unroll
        for (int mi = 0; mi < 2; mi++) {
            const size_t mrow = (size_t)(m0 + wm * 32 + mi * 16 + gid);
            float* o0 = out + mrow * 256 + wn * 64 + tig * 2;
            #pragma unroll
            for (int ni = 0; ni < 8; ni++) {
                float2 v0, v1;
                v0.x = acc[mi][ni][0]; v0.y = acc[mi][ni][1];
                v1.x = acc[mi][ni][2]; v1.y = acc[mi][ni][3];
                *reinterpret_cast<float2*>(o0 + ni * 8)        = v0;   // row m
                *reinterpret_cast<float2*>(o0 + ni * 8 + 2048) = v1;   // row m+8
            }
        }
    }
}

extern "C" void kernel_launch(void* const* d_in, const int* in_sizes, int n_in,
                              void* d_out, int out_size)
{
    const float* t     = (const float*)d_in[0];
    const float* freqs = (const float*)d_in[1];
    const float* As    = (const float*)d_in[2];
    const float* Ac    = (const float*)d_in[3];
    float* out         = (float*)d_out;

    int sm_count = 148;
    cudaDeviceGetAttribute(&sm_count, cudaDevAttrMultiProcessorCount, 0);
    cudaFuncSetAttribute(fourier_mma_kernel,
                         cudaFuncAttributeMaxDynamicSharedMemorySize, SMEM_TOTAL);

    const int rows = in_sizes[0];          // B*L = 262144
    fourier_mma_kernel<<<sm_count, NT, SMEM_TOTAL>>>(t, freqs, As, Ac, out, rows);
}

// round 4
// speedup vs baseline: 1.0815x; 1.0815x over previous
#include <cuda_runtime.h>
#include <cuda_fp16.h>
#include <cstdint>

// ---------------------------------------------------------------------------
// out[m, c] = sum_f sin(2*pi*f*t[m])*As[c,f] + cos(2*pi*f*t[m])*Ac[c,f]
// GEMM: M = 262144, N = 256, K = 256 (K = [sin | cos] halves).
// mma.sync.m16n8k16 fp16->fp32 (tcgen05 PTX rejected on target sm_103).
// Persistent CTAs (1/SM), W fp16 resident in SMEM, X tile DOUBLE-buffered;
// next tile's sincos fill is interleaved between MMA k-steps so the MUFU,
// LSU (ldmatrix) and tensor pipes overlap instead of running in phases.
// ---------------------------------------------------------------------------

#define NT        256
#define MT        64
// SMEM layout (bytes):
//   W : 256 rows(c) x 256 k fp16, 512 B/row, XOR-swizzled -> 131072
//   X0:  64 rows(m) x 256 k fp16                          ->  32768
//   X1:  64 rows(m) x 256 k fp16                          ->  32768
//   F : 128 floats (freqs)                                ->    512
#define SW_OFF     0
#define SX0_OFF    131072
#define SX1_OFF    163840
#define SF_OFF     196608
#define SMEM_TOTAL 197120

static __device__ __forceinline__ uint32_t smem_u32(const void* p) {
    uint32_t a;
    asm("{ .reg .u64 t; cvta.to.shared.u64 t, %1; cvt.u32.u64 %0, t; }"
        : "=r"(a) : "l"(p));
    return a;
}

// byte offset of (row, 16B-chunk) in a 512 B/row tile with XOR swizzle:
// chunk' = chunk ^ (row & 7). Conflict-free for ldmatrix and the fills.
static __device__ __forceinline__ uint32_t swz(uint32_t row, uint32_t chunk) {
    return row * 512u + ((chunk ^ (row & 7u)) << 4);
}

#define LDSM_X4(r, addr) \
    asm volatile("ldmatrix.sync.aligned.m8n8.x4.shared.b16 {%0,%1,%2,%3}, [%4];" \
        : "=r"((r)[0]), "=r"((r)[1]), "=r"((r)[2]), "=r"((r)[3]) : "r"(addr))

#define MMA_16816(d, a, b0, b1) \
    asm volatile("mma.sync.aligned.m16n8k16.row.col.f32.f16.f16.f32 " \
        "{%0,%1,%2,%3}, {%4,%5,%6,%7}, {%8,%9}, {%0,%1,%2,%3};" \
        : "+f"((d)[0]), "+f"((d)[1]), "+f"((d)[2]), "+f"((d)[3]) \
        : "r"((a)[0]), "r"((a)[1]), "r"((a)[2]), "r"((a)[3]), \
          "r"(b0), "r"(b1))

// one fill chunk: 4 freqs -> sin into chunk j, cos into chunk j+16 (k+128)
static __device__ __forceinline__ void fill_chunk(char* xb, const float* sF,
                                                  float tv, int xrow, int f0, int j)
{
    const int f = f0 + j * 4;
    const float4 fr = *reinterpret_cast<const float4*>(sF + f);
    float s0, c0, s1, c1, s2, c2, s3, c3;
    float h, r, th;
    h = tv * fr.x; r = (h + 12582912.0f) - 12582912.0f;
    th = (h - r) * 6.283185307179586f; __sincosf(th, &s0, &c0);
    h = tv * fr.y; r = (h + 12582912.0f) - 12582912.0f;
    th = (h - r) * 6.283185307179586f; __sincosf(th, &s1, &c1);
    h = tv * fr.z; r = (h + 12582912.0f) - 12582912.0f;
    th = (h - r) * 6.283185307179586f; __sincosf(th, &s2, &c2);
    h = tv * fr.w; r = (h + 12582912.0f) - 12582912.0f;
    th = (h - r) * 6.283185307179586f; __sincosf(th, &s3, &c3);

    __half2 hs0 = __floats2half2_rn(s0, s1), hs1 = __floats2half2_rn(s2, s3);
    __half2 hc0 = __floats2half2_rn(c0, c1), hc1 = __floats2half2_rn(c2, c3);

    const uint32_t off = ((uint32_t)(j & 1)) << 3;     // 8B within 16B chunk
    const uint32_t ch  = (uint32_t)(f >> 3);
    uint2 vs, vc;
    vs.x = *reinterpret_cast<uint32_t*>(&hs0);
    vs.y = *reinterpret_cast<uint32_t*>(&hs1);
    vc.x = *reinterpret_cast<uint32_t*>(&hc0);
    vc.y = *reinterpret_cast<uint32_t*>(&hc1);
    *reinterpret_cast<uint2*>(xb + swz((uint32_t)xrow, ch)       + off) = vs;
    *reinterpret_cast<uint2*>(xb + swz((uint32_t)xrow, ch + 16u) + off) = vc;
}

__global__ void __launch_bounds__(NT, 1)
fourier_mma_kernel(const float* __restrict__ t,
                   const float* __restrict__ freqs,
                   const float* __restrict__ As,
                   const float* __restrict__ Ac,
                   float* __restrict__ out,
                   int rows)
{
    extern __shared__ char smem[];
    char* sW  = smem + SW_OFF;
    char* sX[2] = { smem + SX0_OFF, smem + SX1_OFF };
    float* sF = (float*)(smem + SF_OFF);
    const uint32_t uW = smem_u32(sW);
    const uint32_t uX[2] = { smem_u32(sX[0]), smem_u32(sX[1]) };

    const int tid  = threadIdx.x;
    const int lane = tid & 31;
    const int wid  = tid >> 5;

    // ---- one-time: freqs + W fp32->fp16 into swizzled SMEM ----------------
    if (tid < 128) sF[tid] = freqs[tid];
    for (int i = tid; i < 256 * 64; i += NT) {
        const int n  = i >> 6;
        const int j4 = i & 63;
        const int k0 = j4 << 2;
        const float* src = (k0 < 128) ? (As + n * 128 + k0)
                                      : (Ac + n * 128 + (k0 - 128));
        const float4 w = *reinterpret_cast<const float4*>(src);
        __half2 h0 = __floats2half2_rn(w.x, w.y);
        __half2 h1 = __floats2half2_rn(w.z, w.w);
        uint32_t byte = swz((uint32_t)n, (uint32_t)(j4 >> 1)) + ((uint32_t)(j4 & 1) << 3);
        uint2 v;
        v.x = *reinterpret_cast<uint32_t*>(&h0);
        v.y = *reinterpret_cast<uint32_t*>(&h1);
        *reinterpret_cast<uint2*>(sW + byte) = v;
    }

    // ---- per-thread constants ---------------------------------------------
    const int xrow = tid >> 2;                 // X fill: 4 threads per row
    const int f0   = (tid & 3) << 5;           // each covers 32 freqs

    const int wm = wid >> 2;                   // warp grid: 2 (M) x 4 (N)
    const int wn = wid & 3;
    const int gid = lane >> 2, tig = lane & 3;

    const int aRow0   = wm * 32 + (lane & 15);
    const int aHi     = lane >> 4;
    const int bRowOff = (lane & 7) + ((lane >> 4) << 3);
    const int bHi     = (lane >> 3) & 1;

    const int numTiles = rows / MT;
    const int stride   = gridDim.x;
    int tile = blockIdx.x;
    if (tile >= numTiles) return;              // (never on this shape)

    __syncthreads();                           // W + freqs visible

    // ---- prologue: fill buffer 0 for the first tile ------------------------
    {
        const float tv = t[tile * MT + xrow];
        #pragma unroll
        for (int j = 0; j < 8; j++) fill_chunk(sX[0], sF, tv, xrow, f0, j);
    }
    __syncthreads();

    int p = 0;
    for (; tile < numTiles; tile += stride, p ^= 1) {
        const int  nextTile = tile + stride;
        const bool hasNext  = nextTile < numTiles;
        const float tvn = hasNext ? t[nextTile * MT + xrow] : 0.0f;
        char* xnext = sX[p ^ 1];
        const uint32_t uxc = uX[p];
        const int m0 = tile * MT;

        float acc[2][8][4];
        #pragma unroll
        for (int mi = 0; mi < 2; mi++)
            #pragma unroll
            for (int ni = 0; ni < 8; ni++)
                #pragma unroll
                for (int q = 0; q < 4; q++) acc[mi][ni][q] = 0.0f;

        // ---- MMA over K=256 with next-tile fill interleaved ----------------
        #pragma unroll
        for (int ks = 0; ks < 16; ks++) {
            uint32_t a[2][4];
            #pragma unroll
            for (int mi = 0; mi < 2; mi++) {
                const uint32_t row  = (uint32_t)(aRow0 + mi * 16);
                const uint32_t addr = uxc + swz(row, (uint32_t)(ks * 2 + aHi));
                LDSM_X4(a[mi], addr);
            }
            uint32_t b[4][4];
            #pragma unroll
            for (int nt = 0; nt < 4; nt++) {
                const uint32_t n    = (uint32_t)(wn * 64 + nt * 16 + bRowOff);
                const uint32_t addr = uW + swz(n, (uint32_t)(ks * 2 + bHi));
                LDSM_X4(b[nt], addr);
            }
            #pragma unroll
            for (int mi = 0; mi < 2; mi++)
                #pragma unroll
                for (int ni = 0; ni < 8; ni++) {
                    const uint32_t* bb = &b[ni >> 1][(ni & 1) * 2];
                    MMA_16816(acc[mi][ni], a[mi], bb[0], bb[1]);
                }
            if (ks < 8 && hasNext)
                fill_chunk(xnext, sF, tvn, xrow, f0, ks);
        }

        // ---- epilogue: regs -> gmem (STG.64), no SMEM involved --------------
        #pragma unroll
        for (int mi = 0; mi < 2; mi++) {
            const size_t mrow = (size_t)(m0 + wm * 32 + mi * 16 + gid);
            float* o0 = out + mrow * 256 + wn * 64 + tig * 2;
            #pragma unroll
            for (int ni = 0; ni < 8; ni++) {
                float2 v0, v1;
                v0.x = acc[mi][ni][0]; v0.y = acc[mi][ni][1];
                v1.x = acc[mi][ni][2]; v1.y = acc[mi][ni][3];
                *reinterpret_cast<float2*>(o0 + ni * 8)        = v0;   // row m
                *reinterpret_cast<float2*>(o0 + ni * 8 + 2048) = v1;   // row m+8
            }
        }

        // one barrier per tile: MMA reads of buf[p] done before it is refilled
        __syncthreads();
    }
}

extern "C" void kernel_launch(void* const* d_in, const int* in_sizes, int n_in,
                              void* d_out, int out_size)
{
    const float* t     = (const float*)d_in[0];
    const float* freqs = (const float*)d_in[1];
    const float* As    = (const float*)d_in[2];
    const float* Ac    = (const float*)d_in[3];
    float* out         = (float*)d_out;

    int sm_count = 148;
    cudaDeviceGetAttribute(&sm_count, cudaDevAttrMultiProcessorCount, 0);
    cudaFuncSetAttribute(fourier_mma_kernel,
                         cudaFuncAttributeMaxDynamicSharedMemorySize, SMEM_TOTAL);

    const int rows = in_sizes[0];          // B*L = 262144
    fourier_mma_kernel<<<sm_count, NT, SMEM_TOTAL>>>(t, freqs, As, Ac, out, rows);
}

// round 5
// speedup vs baseline: 1.1807x; 1.0917x over previous
#include <cuda_runtime.h>
#include <cuda_fp16.h>
#include <cstdint>

// ---------------------------------------------------------------------------
// out[m, c] = sum_f sin(2*pi*f*t[m])*As[c,f] + cos(2*pi*f*t[m])*Ac[c,f]
// GEMM: M = 262144, N = 256, K = 256 (K = [sin | cos] halves).
// mma.sync.m16n8k16 fp16->fp32. Persistent CTAs (1/SM), W fp16 in SMEM.
// R5: 64x64 warp tiles (M_TILE=128) cut SMEM crossbar traffic 33%;
// single X buffer split by K-half (sin half / cos half) pipelined:
//   phase A: MMA over sin-half  + fill cos-half (same tile)
//   phase B: MMA over cos-half  + fill sin-half (next tile)
// ---------------------------------------------------------------------------

#define NT        256
#define MT        128
// SMEM layout (bytes):
//   W : 256 rows(c) x 256 k fp16, 512 B/row, XOR-swizzled -> 131072
//   X : 128 rows(m) x 256 k fp16, 512 B/row               ->  65536
//   F : 128 floats (freqs)                                ->    512
#define SW_OFF     0
#define SX_OFF     131072
#define SF_OFF     196608
#define SMEM_TOTAL 197120

static __device__ __forceinline__ uint32_t smem_u32(const void* p) {
    uint32_t a;
    asm("{ .reg .u64 t; cvta.to.shared.u64 t, %1; cvt.u32.u64 %0, t; }"
        : "=r"(a) : "l"(p));
    return a;
}

// byte offset of (row, 16B-chunk) in a 512 B/row tile with XOR swizzle:
// chunk' = chunk ^ (row & 7). Conflict-free for ldmatrix and the fills.
static __device__ __forceinline__ uint32_t swz(uint32_t row, uint32_t chunk) {
    return row * 512u + ((chunk ^ (row & 7u)) << 4);
}

#define LDSM_X4(r, addr) \
    asm volatile("ldmatrix.sync.aligned.m8n8.x4.shared.b16 {%0,%1,%2,%3}, [%4];" \
        : "=r"((r)[0]), "=r"((r)[1]), "=r"((r)[2]), "=r"((r)[3]) : "r"(addr))

#define MMA_16816(d, a, b0, b1) \
    asm volatile("mma.sync.aligned.m16n8k16.row.col.f32.f16.f16.f32 " \
        "{%0,%1,%2,%3}, {%4,%5,%6,%7}, {%8,%9}, {%0,%1,%2,%3};" \
        : "+f"((d)[0]), "+f"((d)[1]), "+f"((d)[2]), "+f"((d)[3]) \
        : "r"((a)[0]), "r"((a)[1]), "r"((a)[2]), "r"((a)[3]), \
          "r"(b0), "r"(b1))

// fill 4 freqs of sin (k=f) or cos (k=f+128) for one X row
template <bool USE_COS>
static __device__ __forceinline__ void fill_chunk4(char* xb, const float* sF,
                                                   float tv, int xrow, int f)
{
    const float4 fr = *reinterpret_cast<const float4*>(sF + f);
    float v0, v1, v2, v3, h, r, th;
    h = tv * fr.x; r = (h + 12582912.0f) - 12582912.0f;
    th = (h - r) * 6.283185307179586f; v0 = USE_COS ? __cosf(th) : __sinf(th);
    h = tv * fr.y; r = (h + 12582912.0f) - 12582912.0f;
    th = (h - r) * 6.283185307179586f; v1 = USE_COS ? __cosf(th) : __sinf(th);
    h = tv * fr.z; r = (h + 12582912.0f) - 12582912.0f;
    th = (h - r) * 6.283185307179586f; v2 = USE_COS ? __cosf(th) : __sinf(th);
    h = tv * fr.w; r = (h + 12582912.0f) - 12582912.0f;
    th = (h - r) * 6.283185307179586f; v3 = USE_COS ? __cosf(th) : __sinf(th);

    __half2 h0 = __floats2half2_rn(v0, v1);
    __half2 h1 = __floats2half2_rn(v2, v3);
    const uint32_t ch  = (uint32_t)(f >> 3) + (USE_COS ? 16u : 0u);
    const uint32_t off = ((uint32_t)(f >> 2) & 1u) << 3;   // 8B within chunk
    uint2 v;
    v.x = *reinterpret_cast<uint32_t*>(&h0);
    v.y = *reinterpret_cast<uint32_t*>(&h1);
    *reinterpret_cast<uint2*>(xb + swz((uint32_t)xrow, ch) + off) = v;
}

__global__ void __launch_bounds__(NT, 1)
fourier_mma_kernel(const float* __restrict__ t,
                   const float* __restrict__ freqs,
                   const float* __restrict__ As,
                   const float* __restrict__ Ac,
                   float* __restrict__ out,
                   int rows)
{
    extern __shared__ char smem[];
    char* sW  = smem + SW_OFF;
    char* sX  = smem + SX_OFF;
    float* sF = (float*)(smem + SF_OFF);
    const uint32_t uW = smem_u32(sW);
    const uint32_t uX = smem_u32(sX);

    const int tid  = threadIdx.x;
    const int lane = tid & 31;
    const int wid  = tid >> 5;

    // ---- one-time: freqs + W fp32->fp16 into swizzled SMEM ----------------
    if (tid < 128) sF[tid] = freqs[tid];
    for (int i = tid; i < 256 * 64; i += NT) {
        const int n  = i >> 6;
        const int j4 = i & 63;
        const int k0 = j4 << 2;
        const float* src = (k0 < 128) ? (As + n * 128 + k0)
                                      : (Ac + n * 128 + (k0 - 128));
        const float4 w = *reinterpret_cast<const float4*>(src);
        __half2 h0 = __floats2half2_rn(w.x, w.y);
        __half2 h1 = __floats2half2_rn(w.z, w.w);
        uint32_t byte = swz((uint32_t)n, (uint32_t)(j4 >> 1)) + ((uint32_t)(j4 & 1) << 3);
        uint2 v;
        v.x = *reinterpret_cast<uint32_t*>(&h0);
        v.y = *reinterpret_cast<uint32_t*>(&h1);
        *reinterpret_cast<uint2*>(sW + byte) = v;
    }

    // ---- per-thread constants ---------------------------------------------
    const int xrow = tid >> 1;                 // X fill: 2 threads per row
    const int f0   = (tid & 1) << 6;           // each covers 64 freqs

    const int wm = wid >> 2;                   // warp grid: 2 (M) x 4 (N)
    const int wn = wid & 3;
    const int gid = lane >> 2, tig = lane & 3;

    const int aRow0   = wm * 64 + (lane & 15);
    const int aHi     = lane >> 4;
    const int bRowOff = (lane & 7) + ((lane >> 4) << 3);
    const int bHi     = (lane >> 3) & 1;

    const int numTiles = rows / MT;            // 2048
    const int stride   = gridDim.x;
    int tile = blockIdx.x;
    if (tile >= numTiles) return;

    __syncthreads();                           // W + freqs visible

    // ---- prologue: sin half of first tile ---------------------------------
    {
        const float tv = t[tile * MT + xrow];
        #pragma unroll
        for (int j = 0; j < 16; j++)
            fill_chunk4<false>(sX, sF, tv, xrow, f0 + j * 4);
    }
    __syncthreads();

    for (; tile < numTiles; tile += stride) {
        const int  nextTile = tile + stride;
        const bool hasNext  = nextTile < numTiles;
        const float tvc = t[tile * MT + xrow];                        // cos fill
        const float tvn = hasNext ? t[nextTile * MT + xrow] : 0.0f;   // sin fill
        const int m0 = tile * MT;

        float acc[4][8][4];
        #pragma unroll
        for (int mi = 0; mi < 4; mi++)
            #pragma unroll
            for (int ni = 0; ni < 8; ni++)
                #pragma unroll
                for (int q = 0; q < 4; q++) acc[mi][ni][q] = 0.0f;

        // ==== phase A: MMA ks 0..7 (sin half) + fill cos half of this tile ==
        #pragma unroll
        for (int ks = 0; ks < 8; ks++) {
            uint32_t a[4][4];
            #pragma unroll
            for (int mi = 0; mi < 4; mi++) {
                const uint32_t row  = (uint32_t)(aRow0 + mi * 16);
                LDSM_X4(a[mi], uX + swz(row, (uint32_t)(ks * 2 + aHi)));
            }
            uint32_t b[4][4];
            #pragma unroll
            for (int nt = 0; nt < 4; nt++) {
                const uint32_t n = (uint32_t)(wn * 64 + nt * 16 + bRowOff);
                LDSM_X4(b[nt], uW + swz(n, (uint32_t)(ks * 2 + bHi)));
            }
            #pragma unroll
            for (int mi = 0; mi < 4; mi++)
                #pragma unroll
                for (int ni = 0; ni < 8; ni++) {
                    const uint32_t* bb = &b[ni >> 1][(ni & 1) * 2];
                    MMA_16816(acc[mi][ni], a[mi], bb[0], bb[1]);
                }
            fill_chunk4<true>(sX, sF, tvc, xrow, f0 + ks * 8);
            fill_chunk4<true>(sX, sF, tvc, xrow, f0 + ks * 8 + 4);
        }
        __syncthreads();   // cos half ready; sin half free

        // ==== phase B: MMA ks 8..15 (cos half) + fill sin half of next tile =
        #pragma unroll
        for (int ks = 8; ks < 16; ks++) {
            uint32_t a[4][4];
            #pragma unroll
            for (int mi = 0; mi < 4; mi++) {
                const uint32_t row  = (uint32_t)(aRow0 + mi * 16);
                LDSM_X4(a[mi], uX + swz(row, (uint32_t)(ks * 2 + aHi)));
            }
            uint32_t b[4][4];
            #pragma unroll
            for (int nt = 0; nt < 4; nt++) {
                const uint32_t n = (uint32_t)(wn * 64 + nt * 16 + bRowOff);
                LDSM_X4(b[nt], uW + swz(n, (uint32_t)(ks * 2 + bHi)));
            }
            #pragma unroll
            for (int mi = 0; mi < 4; mi++)
                #pragma unroll
                for (int ni = 0; ni < 8; ni++) {
                    const uint32_t* bb = &b[ni >> 1][(ni & 1) * 2];
                    MMA_16816(acc[mi][ni], a[mi], bb[0], bb[1]);
                }
            if (hasNext) {
                const int j = (ks - 8) * 8;
                fill_chunk4<false>(sX, sF, tvn, xrow, f0 + j);
                fill_chunk4<false>(sX, sF, tvn, xrow, f0 + j + 4);
            }
        }
        __syncthreads();   // sin half of next tile ready; cos half free

        // ==== epilogue: regs -> gmem (STG.64) ===============================
        #pragma unroll
        for (int mi = 0; mi < 4; mi++) {
            const size_t mrow = (size_t)(m0 + wm * 64 + mi * 16 + gid);
            float* o0 = out + mrow * 256 + wn * 64 + tig * 2;
            #pragma unroll
            for (int ni = 0; ni < 8; ni++) {
                float2 v0, v1;
                v0.x = acc[mi][ni][0]; v0.y = acc[mi][ni][1];
                v1.x = acc[mi][ni][2]; v1.y = acc[mi][ni][3];
                *reinterpret_cast<float2*>(o0 + ni * 8)        = v0;   // row m
                *reinterpret_cast<float2*>(o0 + ni * 8 + 2048) = v1;   // row m+8
            }
        }
    }
}

extern "C" void kernel_launch(void* const* d_in, const int* in_sizes, int n_in,
                              void* d_out, int out_size)
{
    const float* t     = (const float*)d_in[0];
    const float* freqs = (const float*)d_in[1];
    const float* As    = (const float*)d_in[2];
    const float* Ac    = (const float*)d_in[3];
    float* out         = (float*)d_out;

    int sm_count = 148;
    cudaDeviceGetAttribute(&sm_count, cudaDevAttrMultiProcessorCount, 0);
    cudaFuncSetAttribute(fourier_mma_kernel,
                         cudaFuncAttributeMaxDynamicSharedMemorySize, SMEM_TOTAL);

    const int rows = in_sizes[0];          // B*L = 262144
    fourier_mma_kernel<<<sm_count, NT, SMEM_TOTAL>>>(t, freqs, As, Ac, out, rows);
}